// round 14
// baseline (speedup 1.0000x reference)
#include <cuda_runtime.h>
#include <cuda_bf16.h>

// Sparsemax along last axis. Input (4,4096,4096) fp32 -> 16384 rows of D=4096.
// One CTA per row; 512 threads x 8 floats (2 float4) register-resident.
// 2 float4/thread (vs 4) cuts the front-batched LDG burst (MLP_p1 16->2),
// collapsing cross-CTA L1tex-queue spread (B300 model) -> fewer DRAM bubbles.
// __ldcs/__stcs: both streams touched exactly once; evict-first keeps L2 clean.
// theta0 = 0.5*(m + m2 - 1) [g(theta0) >= 1 provable], then Michelot/Newton.
// Reductions: warp shfl + 2 barriers, warp0-only second stage (issue-cheap).

#define D      4096
#define NTHR   512
#define NW     16
#define V4     2

__global__ void __launch_bounds__(NTHR, 4)
sparsemax_kernel(const float* __restrict__ in, float* __restrict__ out) {
    __shared__ float s_m[NW];
    __shared__ float s_m2[NW];
    __shared__ float s_s[NW];
    __shared__ float s_c[NW];
    __shared__ float s_b[2];

    const size_t base = (size_t)blockIdx.x * D;
    const float4* rp = reinterpret_cast<const float4*>(in + base);
    float4*       wp = reinterpret_cast<float4*>(out + base);
    const int t    = threadIdx.x;
    const int lane = t & 31;
    const int warp = t >> 5;

    float4 v[V4];
#pragma unroll
    for (int j = 0; j < V4; ++j) v[j] = __ldcs(rp + t + NTHR * j);

    // ---- phase 1: (max, second max) ----
    const float NEG = -3.402823466e+38f;
    float m = NEG, m2 = NEG;
#pragma unroll
    for (int j = 0; j < V4; ++j) {
        float x;
        x = v[j].x; m2 = fmaxf(m2, fminf(m, x)); m = fmaxf(m, x);
        x = v[j].y; m2 = fmaxf(m2, fminf(m, x)); m = fmaxf(m, x);
        x = v[j].z; m2 = fmaxf(m2, fminf(m, x)); m = fmaxf(m, x);
        x = v[j].w; m2 = fmaxf(m2, fminf(m, x)); m = fmaxf(m, x);
    }
#pragma unroll
    for (int o = 16; o > 0; o >>= 1) {
        const float M  = __shfl_xor_sync(0xffffffffu, m,  o);
        const float M2 = __shfl_xor_sync(0xffffffffu, m2, o);
        m2 = fmaxf(fmaxf(m2, M2), fminf(m, M));
        m  = fmaxf(m, M);
    }
    if (lane == 0) { s_m[warp] = m; s_m2[warp] = m2; }
    __syncthreads();
    if (warp == 0) {
        float mm  = s_m[lane & (NW - 1)];
        float mm2 = s_m2[lane & (NW - 1)];
#pragma unroll
        for (int o = NW / 2; o > 0; o >>= 1) {
            const float M  = __shfl_xor_sync(0xffffffffu, mm,  o);
            const float M2 = __shfl_xor_sync(0xffffffffu, mm2, o);
            mm2 = fmaxf(fmaxf(mm2, M2), fminf(mm, M));
            mm  = fmaxf(mm, M);
        }
        // theta0 = 0.5*(m + m2 - 1); valid start for any gap (g(theta0) >= 1)
        if (lane == 0) s_b[0] = 0.5f * (mm + mm2 - 1.0f);
    }
    __syncthreads();
    float theta = s_b[0];

    // ---- phase 2: Newton/Michelot, 2-barrier asymmetric reduction ----
#pragma unroll 1
    for (int it = 0; it < 24; ++it) {
        float s = 0.0f, c = 0.0f;
#pragma unroll
        for (int j = 0; j < V4; ++j) {
            if (v[j].x > theta) { s += v[j].x; c += 1.0f; }
            if (v[j].y > theta) { s += v[j].y; c += 1.0f; }
            if (v[j].z > theta) { s += v[j].z; c += 1.0f; }
            if (v[j].w > theta) { s += v[j].w; c += 1.0f; }
        }
#pragma unroll
        for (int o = 16; o > 0; o >>= 1) {
            s += __shfl_xor_sync(0xffffffffu, s, o);
            c += __shfl_xor_sync(0xffffffffu, c, o);
        }
        if (lane == 0) { s_s[warp] = s; s_c[warp] = c; }
        __syncthreads();
        if (warp == 0) {
            float ss = s_s[lane & (NW - 1)];
            float cc = s_c[lane & (NW - 1)];
#pragma unroll
            for (int o = NW / 2; o > 0; o >>= 1) {
                ss += __shfl_xor_sync(0xffffffffu, ss, o);
                cc += __shfl_xor_sync(0xffffffffu, cc, o);
            }
            if (lane == 0) { s_b[0] = ss; s_b[1] = cc; }
        }
        __syncthreads();
        const float S = s_b[0];
        const float C = s_b[1];            // C >= 1: max always in support
        const float nth = (S - 1.0f) / C;
        if (nth == theta) break;           // uniform decision (same smem inputs everywhere)
        theta = nth;
    }

    // ---- emit p = max(v - theta, 0), streaming store ----
#pragma unroll
    for (int j = 0; j < V4; ++j) {
        float4 o;
        o.x = fmaxf(v[j].x - theta, 0.0f);
        o.y = fmaxf(v[j].y - theta, 0.0f);
        o.z = fmaxf(v[j].z - theta, 0.0f);
        o.w = fmaxf(v[j].w - theta, 0.0f);
        __stcs(wp + t + NTHR * j, o);
    }
}

extern "C" void kernel_launch(void* const* d_in, const int* in_sizes, int n_in,
                              void* d_out, int out_size) {
    const float* in = (const float*)d_in[0];
    float* out = (float*)d_out;
    const int rows = in_sizes[0] / D;   // 16384
    sparsemax_kernel<<<rows, NTHR>>>(in, out);
}